// round 10
// baseline (speedup 1.0000x reference)
#include <cuda_runtime.h>

// out[i, h=n*7+o, m] = sum_{j<48,k<3} W[i,j*3+k] * x[j, n*7+(o+k-1), m]
//   (term dropped when o+k-1 outside [0,7))
// x: (48,56,56) f32   W: (192,48,3) f32   out: (192,56,56) f32
//
// Block = 32 i x 56 m for one h. lane = i  ->  x loads warp-uniform (broadcast),
// W row staged through registers in chunks, zero FFMA padding waste.

#define JCH 48
#define KTAP 3
#define MW 56
#define BI 32
#define WPAD 148          // W smem row stride in floats: gcd(37,32)=1 -> conflict-free f4
#define NTHREADS 448      // 32 i * 14 m-quads
#define XSLAB (KTAP * JCH * MW)   // 8064 floats
#define JC 8              // j per register chunk (24 W values = 6 f4)

__global__ __launch_bounds__(NTHREADS)
void fold_conv_kernel(const float* __restrict__ x,
                      const float* __restrict__ W,
                      float* __restrict__ out)
{
    extern __shared__ float sm[];
    float* xs  = sm;                  // [KTAP*JCH][56] = 8064 floats (31.5 KB)
    float* wsm = sm + XSLAB;          // [BI][WPAD]     = 4736 floats (18.5 KB)

    const int tid = threadIdx.x;
    const int h  = blockIdx.x;        // 0..55
    const int n  = h / 7;
    const int o  = h - n * 7;
    const int i0 = blockIdx.y * BI;   // 0..160 step 32

    // ---- x slab: 144 rows x 14 f4, coalesced, zero-padded taps ----
    #pragma unroll
    for (int it = 0; it < 5; ++it) {
        int idx = tid + it * NTHREADS;            // f4 index, 0..2015
        if (idx < KTAP * JCH * 14) {
            int row = idx / 14;                   // k*48+j
            int s   = idx - row * 14;             // f4 slot
            int k   = row / JCH;
            int j   = row - k * JCH;
            int r   = o + k - 1;
            float4 v = make_float4(0.f, 0.f, 0.f, 0.f);
            if (r >= 0 && r < 7)
                v = *(const float4*)&x[(j * 56 + n * 7 + r) * 56 + s * 4];
            // row stride 56 floats = 224 B (16B aligned)
            *(float4*)&xs[row * MW + s * 4] = v;
        }
    }
    // ---- W tile: 32 rows x 36 f4, coalesced read, padded-row smem ----
    #pragma unroll
    for (int it = 0; it < 3; ++it) {
        int idx = tid + it * NTHREADS;            // f4 index, 0..1151
        if (idx < BI * 36) {
            int ii = idx / 36;
            int q  = idx - ii * 36;
            float4 v = *(const float4*)&W[(i0 + ii) * (JCH * KTAP) + q * 4];
            *(float4*)&wsm[ii * WPAD + q * 4] = v;
        }
    }
    __syncthreads();

    // ---- mainloop: lane = i, warp = m-quad ----
    const int lane = tid & 31;                    // i within tile
    const int mq   = tid >> 5;                    // 0..13
    const int m0   = mq * 4;

    float acc0 = 0.f, acc1 = 0.f, acc2 = 0.f, acc3 = 0.f;
    const float* wrow = wsm + lane * WPAD;
    const float* xb   = xs + m0;

    #pragma unroll 1
    for (int c = 0; c < JCH / JC; ++c) {          // 6 chunks
        float wreg[JC * 3];                       // 24 W values in registers
        #pragma unroll
        for (int q = 0; q < 6; ++q)
            *(float4*)&wreg[q * 4] = *(const float4*)&wrow[c * (JC * 3) + q * 4];
        #pragma unroll
        for (int jj = 0; jj < JC; ++jj) {
            const int j = c * JC + jj;
            const float4 x0 = *(const float4*)&xb[(0 * JCH + j) * MW];
            const float4 x1 = *(const float4*)&xb[(1 * JCH + j) * MW];
            const float4 x2 = *(const float4*)&xb[(2 * JCH + j) * MW];
            const float w0 = wreg[jj * 3 + 0];
            const float w1 = wreg[jj * 3 + 1];
            const float w2 = wreg[jj * 3 + 2];
            acc0 = fmaf(w0, x0.x, acc0); acc1 = fmaf(w0, x0.y, acc1);
            acc2 = fmaf(w0, x0.z, acc2); acc3 = fmaf(w0, x0.w, acc3);
            acc0 = fmaf(w1, x1.x, acc0); acc1 = fmaf(w1, x1.y, acc1);
            acc2 = fmaf(w1, x1.z, acc2); acc3 = fmaf(w1, x1.w, acc3);
            acc0 = fmaf(w2, x2.x, acc0); acc1 = fmaf(w2, x2.y, acc1);
            acc2 = fmaf(w2, x2.z, acc2); acc3 = fmaf(w2, x2.w, acc3);
        }
    }

    // ---- epilogue: transpose through smem, then 1 coalesced f4 STG/thread ----
    __syncthreads();                              // slab no longer needed
    {
        float* osm = sm;                          // [BI][60]
        float4 v = {acc0, acc1, acc2, acc3};
        *(float4*)&osm[lane * 60 + m0] = v;       // bank(i*15+q): gcd(15,32)=1
    }
    __syncthreads();
    {
        const float* osm = sm;
        int ii = tid / 14;                        // 0..31
        int fq = tid - ii * 14;                   // 0..13
        float4 v = *(const float4*)&osm[ii * 60 + fq * 4];
        *(float4*)&out[(i0 + ii) * 3136 + h * 56 + fq * 4] = v;
    }
}

extern "C" void kernel_launch(void* const* d_in, const int* in_sizes, int n_in,
                              void* d_out, int out_size)
{
    const float* x = (const float*)d_in[0];   // 48*56*56
    const float* W = (const float*)d_in[1];   // 192*48*3
    float* out = (float*)d_out;               // 192*56*56

    const int smem = (XSLAB + BI * WPAD) * (int)sizeof(float); // 51200 B
    static bool attr_set = false;
    if (!attr_set) {
        cudaFuncSetAttribute(fold_conv_kernel,
                             cudaFuncAttributeMaxDynamicSharedMemorySize, smem);
        attr_set = true;
    }
    dim3 grid(56, 6);
    fold_conv_kernel<<<grid, NTHREADS, smem>>>(x, W, out);
}